// round 2
// baseline (speedup 1.0000x reference)
#include <cuda_runtime.h>

#define NXg 1024
#define NYg 85
#define N_AMPS 1500
#define NPIX (NXg * NYg)

__global__ __launch_bounds__(256)
void echellogram_kernel(
    const int*   __restrict__ index_p,     // d_in[0]
    const float* __restrict__ bkg_p,       // d_in[1]
    const float* __restrict__ s_coeffs,    // d_in[2] (3)
    const float* __restrict__ amps,        // d_in[3] (1500)
    const float* __restrict__ smooth_p,    // d_in[4]
    const float* __restrict__ lam_coeffs,  // d_in[5] (4)
    const float* __restrict__ p_coeffs,    // d_in[6] (2x2)
    const float* __restrict__ src_amps,    // d_in[7] (1500)
    const float* __restrict__ fiducial,    // d_in[8] (2)
    const float* __restrict__ lam_vector,  // d_in[9] (1500)
    float*       __restrict__ out)
{
    const float SIGMA        = 0.42f;
    const float INV_SIGMA    = 1.0f / 0.42f;
    const float SLIT         = 12.0f;
    const float INV_SQRT_2PI = 0.3989422804014327f;
    const float LOG_SQRT_2PI = 0.9189385332046727f;

    int t = blockIdx.x * blockDim.x + threadIdx.x;
    int i = t >> 1;          // pixel id
    int h = t & 1;           // which half of the amp window this thread sums
    if (i >= NPIX) return;

    int x = i / NYg;
    int y = i - x * NYg;
    float xf = (float)x;
    float yf = (float)y;

    // --- scalar params (broadcast L1 loads) ---
    int   idx        = index_p[0];
    float bkg        = bkg_p[0];
    float smoothness = smooth_p[0];
    float s0 = s_coeffs[0], s1 = s_coeffs[1], s2 = s_coeffs[2];
    float c0 = lam_coeffs[0], c1 = lam_coeffs[1], c2 = lam_coeffs[2], c3 = lam_coeffs[3];
    float f0 = fiducial[0],   f1 = fiducial[1];
    float pc0 = p_coeffs[2 * idx + 0];
    float pc1 = p_coeffs[2 * idx + 1];

    // --- along-slit coordinate & wavelength surface (ref op order) ---
    float ss = s1 * (yf - s0 - s2 * xf);

    float xn = (xf - 512.0f) / 512.0f;
    float yn = (yf - 42.5f) / 42.5f;
    float cx1 = f1 * (1.0f + c1 * 0.01f) * 512.0f;
    float cx2 = 1.0f + c2;
    float lam = f0 + c0 + cx1 * xn + cx2 * (2.0f * xn * xn - 1.0f) + c3 * yn;

    // --- soft slit mask ---
    float inv_beta = __expf(-smoothness);
    float e1 = 1.0f / (1.0f + __expf(-(ss * inv_beta)));
    float e2 = 1.0f / (1.0f + __expf(-((SLIT - ss) * inv_beta)));
    float emask = e1 * e2;

    // --- windowed Gaussian-comb reduction over amps axis ---
    float lam0 = lam_vector[0];
    float lamN = lam_vector[N_AMPS - 1];
    float dlam = (lamN - lam0) * (1.0f / (float)(N_AMPS - 1));

    int lo = 0, hi = N_AMPS - 1;
    if (fabsf(dlam) > 1e-20f) {
        float inv_dlam = 1.0f / dlam;
        float tc = (lam - lam0) * inv_dlam;           // fractional center index
        float hw = 5.5f * SIGMA * fabsf(inv_dlam);    // 5.5-sigma half-window
        lo = max(0,          (int)floorf(tc - hw));
        hi = min(N_AMPS - 1, (int)ceilf (tc + hw));
    }

    // stride-2 split: thread h sums a = lo+h, lo+h+2, ...
    float sky = 0.0f, src = 0.0f;
    #pragma unroll 4
    for (int a = lo + h; a <= hi; a += 2) {
        float z = (lam - lam_vector[a]) * INV_SIGMA;
        float p = __expf(-0.5f * z * z);
        sky = fmaf(amps[a],     p, sky);
        src = fmaf(src_amps[a], p, src);
    }
    // combine lane pairs (2j <-> 2j+1)
    sky += __shfl_xor_sync(0xffffffffu, sky, 1);
    src += __shfl_xor_sync(0xffffffffu, src, 1);

    float norm = INV_SQRT_2PI * INV_SIGMA;
    sky *= norm;
    src *= norm;

    // --- source spatial profile ---
    float sig_s = __expf(pc1);
    float u = (ss - pc0) / sig_s;
    float src_prof = __expf(fmaf(-0.5f * u, u, -pc1 - LOG_SQRT_2PI));

    if (h == 0)
        out[i] = emask * sky + src_prof * src + bkg;
}

extern "C" void kernel_launch(void* const* d_in, const int* in_sizes, int n_in,
                              void* d_out, int out_size) {
    (void)in_sizes; (void)n_in; (void)out_size;
    const int*   index_p    = (const int*)  d_in[0];
    const float* bkg_p      = (const float*)d_in[1];
    const float* s_coeffs   = (const float*)d_in[2];
    const float* amps       = (const float*)d_in[3];
    const float* smooth_p   = (const float*)d_in[4];
    const float* lam_coeffs = (const float*)d_in[5];
    const float* p_coeffs   = (const float*)d_in[6];
    const float* src_amps   = (const float*)d_in[7];
    const float* fiducial   = (const float*)d_in[8];
    const float* lam_vector = (const float*)d_in[9];
    float* out = (float*)d_out;

    const int total = NPIX * 2;            // 174080 threads, 2 per pixel
    const int threads = 256;
    const int blocks = (total + threads - 1) / threads;  // 680
    echellogram_kernel<<<blocks, threads>>>(
        index_p, bkg_p, s_coeffs, amps, smooth_p, lam_coeffs,
        p_coeffs, src_amps, fiducial, lam_vector, out);
}

// round 3
// speedup vs baseline: 1.0566x; 1.0566x over previous
#include <cuda_runtime.h>

#define NXg 1024
#define NYg 85
#define N_AMPS 1500
#define NPIX (NXg * NYg)

__global__ __launch_bounds__(128)
void echellogram_kernel(
    const int*   __restrict__ index_p,     // d_in[0]
    const float* __restrict__ bkg_p,       // d_in[1]
    const float* __restrict__ s_coeffs,    // d_in[2] (3)
    const float* __restrict__ amps,        // d_in[3] (1500)
    const float* __restrict__ smooth_p,    // d_in[4]
    const float* __restrict__ lam_coeffs,  // d_in[5] (4)
    const float* __restrict__ p_coeffs,    // d_in[6] (2x2)
    const float* __restrict__ src_amps,    // d_in[7] (1500)
    const float* __restrict__ fiducial,    // d_in[8] (2)
    const float* __restrict__ lam_vector,  // d_in[9] (1500)
    float*       __restrict__ out)
{
    const float SIGMA        = 0.42f;
    const float INV_SIGMA    = 1.0f / 0.42f;
    const float SLIT         = 12.0f;
    const float INV_SQRT_2PI = 0.3989422804014327f;
    const float LOG_SQRT_2PI = 0.9189385332046727f;

    int i = blockIdx.x * blockDim.x + threadIdx.x;
    if (i >= NPIX) return;
    int x = i / NYg;
    int y = i - x * NYg;
    float xf = (float)x;
    float yf = (float)y;

    // --- scalar params (broadcast L1 loads) ---
    int   idx        = index_p[0];
    float bkg        = bkg_p[0];
    float smoothness = smooth_p[0];
    float s0 = s_coeffs[0], s1 = s_coeffs[1], s2 = s_coeffs[2];
    float c0 = lam_coeffs[0], c1 = lam_coeffs[1], c2 = lam_coeffs[2], c3 = lam_coeffs[3];
    float f0 = fiducial[0],   f1 = fiducial[1];
    float pc0 = p_coeffs[2 * idx + 0];
    float pc1 = p_coeffs[2 * idx + 1];

    // --- along-slit coordinate & wavelength surface (ref op order) ---
    float ss = s1 * (yf - s0 - s2 * xf);

    float xn = (xf - 512.0f) / 512.0f;
    float yn = (yf - 42.5f) / 42.5f;
    float cx1 = f1 * (1.0f + c1 * 0.01f) * 512.0f;
    float cx2 = 1.0f + c2;
    float lam = f0 + c0 + cx1 * xn + cx2 * (2.0f * xn * xn - 1.0f) + c3 * yn;

    // --- soft slit mask ---
    float inv_beta = __expf(-smoothness);
    float e1 = 1.0f / (1.0f + __expf(-(ss * inv_beta)));
    float e2 = 1.0f / (1.0f + __expf(-((SLIT - ss) * inv_beta)));
    float emask = e1 * e2;

    // --- windowed Gaussian-comb reduction, float4 chunks of the amps axis ---
    float lam0 = lam_vector[0];
    float lamN = lam_vector[N_AMPS - 1];
    float dlam = (lamN - lam0) * (1.0f / (float)(N_AMPS - 1));

    int lo = 0, hi = N_AMPS - 1;
    if (fabsf(dlam) > 1e-20f) {
        float inv_dlam = 1.0f / dlam;
        float tc = (lam - lam0) * inv_dlam;           // fractional center index
        float hw = 5.5f * SIGMA * fabsf(inv_dlam);    // 5.5-sigma half-window
        lo = max(0,          (int)floorf(tc - hw));
        hi = min(N_AMPS - 1, (int)ceilf (tc + hw));
    }
    int k0 = lo >> 2;            // 4-aligned chunk range (1500 % 4 == 0 -> in bounds)
    int k1 = hi >> 2;

    const float4* __restrict__ lam4 = (const float4*)lam_vector;
    const float4* __restrict__ amp4 = (const float4*)amps;
    const float4* __restrict__ srv4 = (const float4*)src_amps;

    float sky0 = 0.0f, sky1 = 0.0f, src0 = 0.0f, src1 = 0.0f;
    #pragma unroll 2
    for (int k = k0; k <= k1; ++k) {
        float4 lv = lam4[k];
        float4 av = amp4[k];
        float4 sv = srv4[k];
        float z0 = (lam - lv.x) * INV_SIGMA;
        float z1 = (lam - lv.y) * INV_SIGMA;
        float z2 = (lam - lv.z) * INV_SIGMA;
        float z3 = (lam - lv.w) * INV_SIGMA;
        float p0 = __expf(-0.5f * z0 * z0);
        float p1 = __expf(-0.5f * z1 * z1);
        float p2 = __expf(-0.5f * z2 * z2);
        float p3 = __expf(-0.5f * z3 * z3);
        sky0 = fmaf(av.x, p0, sky0);
        sky1 = fmaf(av.y, p1, sky1);
        sky0 = fmaf(av.z, p2, sky0);
        sky1 = fmaf(av.w, p3, sky1);
        src0 = fmaf(sv.x, p0, src0);
        src1 = fmaf(sv.y, p1, src1);
        src0 = fmaf(sv.z, p2, src0);
        src1 = fmaf(sv.w, p3, src1);
    }
    float norm = INV_SQRT_2PI * INV_SIGMA;
    float sky = (sky0 + sky1) * norm;
    float src = (src0 + src1) * norm;

    // --- source spatial profile ---
    float sig_s = __expf(pc1);
    float u = (ss - pc0) / sig_s;
    float src_prof = __expf(fmaf(-0.5f * u, u, -pc1 - LOG_SQRT_2PI));

    out[i] = emask * sky + src_prof * src + bkg;
}

extern "C" void kernel_launch(void* const* d_in, const int* in_sizes, int n_in,
                              void* d_out, int out_size) {
    (void)in_sizes; (void)n_in; (void)out_size;
    const int*   index_p    = (const int*)  d_in[0];
    const float* bkg_p      = (const float*)d_in[1];
    const float* s_coeffs   = (const float*)d_in[2];
    const float* amps       = (const float*)d_in[3];
    const float* smooth_p   = (const float*)d_in[4];
    const float* lam_coeffs = (const float*)d_in[5];
    const float* p_coeffs   = (const float*)d_in[6];
    const float* src_amps   = (const float*)d_in[7];
    const float* fiducial   = (const float*)d_in[8];
    const float* lam_vector = (const float*)d_in[9];
    float* out = (float*)d_out;

    const int threads = 128;
    const int blocks = (NPIX + threads - 1) / threads;   // 680
    echellogram_kernel<<<blocks, threads>>>(
        index_p, bkg_p, s_coeffs, amps, smooth_p, lam_coeffs,
        p_coeffs, src_amps, fiducial, lam_vector, out);
}

// round 4
// speedup vs baseline: 1.3527x; 1.2802x over previous
#include <cuda_runtime.h>

#define NXg 1024
#define NYg 85
#define N_AMPS 1500
#define NCH 375          // N_AMPS / 4 chunks
#define WCHUNKS 7        // fixed window: 7 float4 chunks = 28 amps >= 23 needed

__device__ __forceinline__ float ex2f(float x) {
    float r;
    asm("ex2.approx.ftz.f32 %0, %1;" : "=f"(r) : "f"(x));
    return r;
}

__global__ __launch_bounds__(96)
void echellogram_kernel(
    const int*   __restrict__ index_p,
    const float* __restrict__ bkg_p,
    const float* __restrict__ s_coeffs,
    const float* __restrict__ amps,
    const float* __restrict__ smooth_p,
    const float* __restrict__ lam_coeffs,
    const float* __restrict__ p_coeffs,
    const float* __restrict__ src_amps,
    const float* __restrict__ fiducial,
    const float* __restrict__ lam_vector,
    float*       __restrict__ out)
{
    const float SIGMA        = 0.42f;
    const float INV_SIGMA    = 1.0f / 0.42f;
    const float SLIT         = 12.0f;
    const float INV_SQRT_2PI = 0.3989422804014327f;
    const float LOG_SQRT_2PI = 0.9189385332046727f;
    const float LOG2E        = 1.4426950408889634f;

    int x = blockIdx.x;
    int y = threadIdx.x;
    if (y >= NYg) return;
    float xf = (float)x;
    float yf = (float)y;

    // --- scalar params; issue the dependent chain (index -> p_coeffs) first ---
    int   idx        = index_p[0];
    float lam0_v     = lam_vector[0];
    float lamN_v     = lam_vector[N_AMPS - 1];
    float bkg        = bkg_p[0];
    float smoothness = smooth_p[0];
    float s0 = s_coeffs[0], s1 = s_coeffs[1], s2 = s_coeffs[2];
    float c0 = lam_coeffs[0], c1 = lam_coeffs[1], c2 = lam_coeffs[2], c3 = lam_coeffs[3];
    float f0 = fiducial[0],   f1 = fiducial[1];
    float pc0 = p_coeffs[2 * idx + 0];
    float pc1 = p_coeffs[2 * idx + 1];

    // --- along-slit coordinate & wavelength surface (ref op order) ---
    float ss = s1 * (yf - s0 - s2 * xf);

    float xn = (xf - 512.0f) / 512.0f;
    float yn = (yf - 42.5f) / 42.5f;
    float cx1 = f1 * (1.0f + c1 * 0.01f) * 512.0f;
    float cx2 = 1.0f + c2;
    float lam = f0 + c0 + cx1 * xn + cx2 * (2.0f * xn * xn - 1.0f) + c3 * yn;

    // --- window placement ---
    float dlam = (lamN_v - lam0_v) * (1.0f / (float)(N_AMPS - 1));
    int k0 = 0, k1 = 0;                 // chunk range; [k0, k0+WCHUNKS) fixed part
    bool tiny_dlam = (fabsf(dlam) <= 1e-20f);
    if (!tiny_dlam) {
        float inv_dlam = 1.0f / dlam;
        float tc = (lam - lam0_v) * inv_dlam;
        float hw = 5.5f * SIGMA * fabsf(inv_dlam);
        int lo = max(0,          (int)floorf(tc - hw));
        int hi = min(N_AMPS - 1, (int)ceilf (tc + hw));
        k0 = min(max(lo >> 2, 0), NCH - WCHUNKS);
        k1 = hi >> 2;                   // tail loop below covers k1 > k0+WCHUNKS-1
    } else {
        k0 = 0; k1 = NCH - 1;           // degenerate: sum everything
    }

    const float4* __restrict__ lam4 = (const float4*)lam_vector;
    const float4* __restrict__ amp4 = (const float4*)amps;
    const float4* __restrict__ srv4 = (const float4*)src_amps;

    const float A = 0.5f * LOG2E * INV_SIGMA * INV_SIGMA;   // p = 2^(-A d^2)

    float sky0 = 0.0f, sky1 = 0.0f, src0 = 0.0f, src1 = 0.0f;
    #pragma unroll
    for (int k = 0; k < WCHUNKS; ++k) {
        int a = k0 + k;
        float4 lv = lam4[a];
        float4 av = amp4[a];
        float4 sv = srv4[a];
        float d0 = lam - lv.x;
        float d1 = lam - lv.y;
        float d2 = lam - lv.z;
        float d3 = lam - lv.w;
        float p0 = ex2f(-A * d0 * d0);
        float p1 = ex2f(-A * d1 * d1);
        float p2 = ex2f(-A * d2 * d2);
        float p3 = ex2f(-A * d3 * d3);
        sky0 = fmaf(av.x, p0, sky0);
        sky1 = fmaf(av.y, p1, sky1);
        sky0 = fmaf(av.z, p2, sky0);
        sky1 = fmaf(av.w, p3, sky1);
        src0 = fmaf(sv.x, p0, src0);
        src1 = fmaf(sv.y, p1, src1);
        src0 = fmaf(sv.z, p2, src0);
        src1 = fmaf(sv.w, p3, src1);
    }
    // generic tail (never taken for the benchmark's dlam; keeps correctness general)
    for (int a = k0 + WCHUNKS; a <= k1; ++a) {
        float4 lv = lam4[a];
        float4 av = amp4[a];
        float4 sv = srv4[a];
        float d0 = lam - lv.x, d1 = lam - lv.y, d2 = lam - lv.z, d3 = lam - lv.w;
        float p0 = ex2f(-A * d0 * d0);
        float p1 = ex2f(-A * d1 * d1);
        float p2 = ex2f(-A * d2 * d2);
        float p3 = ex2f(-A * d3 * d3);
        sky0 = fmaf(av.x, p0, sky0);
        sky1 = fmaf(av.y, p1, sky1);
        sky0 = fmaf(av.z, p2, sky0);
        sky1 = fmaf(av.w, p3, sky1);
        src0 = fmaf(sv.x, p0, src0);
        src1 = fmaf(sv.y, p1, src1);
        src0 = fmaf(sv.z, p2, src0);
        src1 = fmaf(sv.w, p3, src1);
    }

    float norm = INV_SQRT_2PI * INV_SIGMA;
    float sky = (sky0 + sky1) * norm;
    float src = (src0 + src1) * norm;

    // --- soft slit mask (sigmoids via ex2) ---
    float inv_beta = ex2f(-smoothness * LOG2E);
    float e1 = 1.0f / (1.0f + ex2f(-(ss * inv_beta) * LOG2E));
    float e2 = 1.0f / (1.0f + ex2f(-((SLIT - ss) * inv_beta) * LOG2E));
    float emask = e1 * e2;

    // --- source spatial profile ---
    float sig_s = ex2f(pc1 * LOG2E);
    float u = (ss - pc0) / sig_s;
    float src_prof = ex2f(fmaf(-0.5f * u, u, -pc1 - LOG_SQRT_2PI) * LOG2E);

    out[x * NYg + y] = emask * sky + src_prof * src + bkg;
}

extern "C" void kernel_launch(void* const* d_in, const int* in_sizes, int n_in,
                              void* d_out, int out_size) {
    (void)in_sizes; (void)n_in; (void)out_size;
    const int*   index_p    = (const int*)  d_in[0];
    const float* bkg_p      = (const float*)d_in[1];
    const float* s_coeffs   = (const float*)d_in[2];
    const float* amps       = (const float*)d_in[3];
    const float* smooth_p   = (const float*)d_in[4];
    const float* lam_coeffs = (const float*)d_in[5];
    const float* p_coeffs   = (const float*)d_in[6];
    const float* src_amps   = (const float*)d_in[7];
    const float* fiducial   = (const float*)d_in[8];
    const float* lam_vector = (const float*)d_in[9];
    float* out = (float*)d_out;

    echellogram_kernel<<<NXg, 96>>>(
        index_p, bkg_p, s_coeffs, amps, smooth_p, lam_coeffs,
        p_coeffs, src_amps, fiducial, lam_vector, out);
}